// round 14
// baseline (speedup 1.0000x reference)
#include <cuda_runtime.h>
#include <math.h>

// DDSL spec: B=2, NV=NE=512, RES=(128,128) -> freq grid 128 x 65, J=2.
// Direct packed kernel, two adjacent fx freqs (kx,kx+1) per thread (f32x2).
// One warp per freq-pair; 16 edges per lane split into two independent
// 8-edge ring chains. KEY: t_hi = t_lo + x with x freq-independent, so the
// hi phase is derived from the lo sincos by a complex rotation with the
// PRECOMPUTED per-vertex (cos 2pi x, sin 2pi x) -> 1 sincos + 1 rcp per
// edge (3 MUFU/STEP instead of 5). Single product-rcp divide, dlo sanitized.

#define NV      512
#define NE      512
#define FX      128
#define FY2     65
#define NFP     (FX / 2 * FY2)      // 4160 fx-pairs
#define GROUPS  8                   // freq-pairs (warps) per block
#define BLOCK   256
#define EPC     8                   // edges per chain (2 chains per lane)

typedef unsigned long long u64;

__device__ __forceinline__ u64 pk2(float a, float b) {
    u64 r; asm("mov.b64 %0, {%1, %2};" : "=l"(r) : "f"(a), "f"(b)); return r;
}
__device__ __forceinline__ void upk(u64 v, float& a, float& b) {
    asm("mov.b64 {%0, %1}, %2;" : "=f"(a), "=f"(b) : "l"(v));
}
__device__ __forceinline__ u64 f2fma(u64 a, u64 b, u64 c) {
    u64 d; asm("fma.rn.f32x2 %0, %1, %2, %3;" : "=l"(d) : "l"(a), "l"(b), "l"(c)); return d;
}
__device__ __forceinline__ u64 f2add(u64 a, u64 b) {
    u64 d; asm("add.rn.f32x2 %0, %1, %2;" : "=l"(d) : "l"(a), "l"(b)); return d;
}
__device__ __forceinline__ u64 f2mul(u64 a, u64 b) {
    u64 d; asm("mul.rn.f32x2 %0, %1, %2;" : "=l"(d) : "l"(a), "l"(b)); return d;
}

__device__ __forceinline__ float fracr(float t) {
    const float MAGIC = 12582912.0f;  // 1.5 * 2^23
    float g = __fadd_rn(t, MAGIC);
    float r = __fadd_rn(g, -MAGIC);
    return t - r;
}

__global__ __launch_bounds__(BLOCK, 4)
void ddsl_spec_kernel(const float* __restrict__ V,
                      const int*   __restrict__ E,
                      const float* __restrict__ D,
                      float*       __restrict__ out)
{
    // pad-every-16 layout: idx(e) = e + (e>>4); lane group stride = 17.
    __shared__ float2 sXY[546];    // (x, y);      idx(512)=544 = wrap dup
    __shared__ float2 sCS[546];    // (cos2pix, sin2pix) per vertex
    __shared__ float  sCD[544];    // C*D per edge

    const int b = blockIdx.y;
    const float TWO_PI = 6.28318530717958647692f;

    // ---- stage ring vertices + per-vertex x-phase + C*D ----
    for (int e = threadIdx.x; e < NE; e += BLOCK) {
        int i0 = E[(b * NE + e) * 2 + 0];
        int i1 = E[(b * NE + e) * 2 + 1];
        float ax = V[(b * NV + i0) * 2 + 0];
        float ay = V[(b * NV + i0) * 2 + 1];
        float bx = V[(b * NV + i1) * 2 + 0];
        float by = V[(b * NV + i1) * 2 + 1];
        int p = e + (e >> 4);
        sXY[p] = make_float2(ax, ay);
        float sxv, cxv;
        __sincosf(fracr(ax) * TWO_PI, &sxv, &cxv);   // sin first, cos second
        sCS[p] = make_float2(cxv, sxv);
        sCD[p] = (ax * by - ay * bx) * D[b * NE + e];
        if (e == 0) {
            sXY[544] = make_float2(ax, ay);
            sCS[544] = make_float2(cxv, sxv);
        }
    }
    __syncthreads();

    const int lane = threadIdx.x & 31;
    const int fp   = blockIdx.x * GROUPS + (threadIdx.x >> 5);

    const int fxp = fp / FY2;
    const int fy  = fp - fxp * FY2;
    const int fx0 = 2 * fxp;
    const int kx0 = (fx0 < FX / 2) ? fx0 : fx0 - FX;   // kx1 = kx0 + 1
    const float fkx = (float)kx0;
    const float fky = (float)fy;

    const u64 NEG1 = pk2(-1.0f, -1.0f);

    // lane's 16-edge chunk: index 17*lane + j (j = 0..15), ring-wrap at 17.
    const float2* xyb = &sXY[17 * lane];
    const float2* csb = &sCS[17 * lane];
    const float*  cb  = &sCD[17 * lane];

#define INITV(OFS, T, C, S)                                                \
    {                                                                      \
        float2 v  = xyb[OFS];                                              \
        float2 cs = csb[OFS];                                              \
        float tl = fmaf(v.y, fky, v.x * fkx);                              \
        float sl, cl;                                                      \
        __sincosf(fracr(tl) * TWO_PI, &sl, &cl);                           \
        float chh = fmaf(cl, cs.x, -sl * cs.y);                            \
        float shh = fmaf(sl, cs.x,  cl * cs.y);                            \
        T = pk2(tl, tl + v.x); C = pk2(cl, chh); S = pk2(sl, shh);         \
    }

#define STEP(T, C, S, OFS, CDOFS, AR, AI)                                  \
    {                                                                      \
        float2 nv = xyb[OFS];                                              \
        float2 cs = csb[OFS];                                              \
        float cd  = cb[CDOFS];                                             \
        float tl = fmaf(nv.y, fky, nv.x * fkx);                            \
        float sl, cl;                                                      \
        __sincosf(fracr(tl) * TWO_PI, &sl, &cl);                           \
        float chh = fmaf(cl, cs.x, -sl * cs.y);                            \
        float shh = fmaf(sl, cs.x,  cl * cs.y);                            \
        u64 T1  = pk2(tl, tl + nv.x);                                      \
        u64 CS1 = pk2(cl, chh);                                            \
        u64 SN1 = pk2(sl, shh);                                            \
        u64 dt  = f2fma(T1, NEG1, T);                                      \
        u64 den = f2mul(f2mul(T, T1), dt);                                 \
        u64 nt  = f2mul(T, NEG1);                                          \
        u64 nr  = f2fma(CS1, nt, f2fma(C, T1, dt));                        \
        u64 ni  = f2fma(SN1, nt, f2mul(S, T1));                            \
        float dlo, dhi; upk(den, dlo, dhi);                                \
        dlo = (dlo == 0.0f) ? 1.0f : dlo;                                  \
        float rp = __fdividef(cd, dlo * dhi);                              \
        u64 rc = pk2(rp * dhi, rp * dlo);                                  \
        AR = f2fma(nr, rc, AR);                                            \
        AI = f2fma(ni, rc, AI);                                            \
        T = T1; C = CS1; S = SN1;                                          \
    }

    u64 aR0 = pk2(0.0f, 0.0f), aI0 = pk2(0.0f, 0.0f);
    u64 aR1 = pk2(0.0f, 0.0f), aI1 = pk2(0.0f, 0.0f);

    u64 TA, CA, SA, TB, CB, SB;
    INITV(0, TA, CA, SA);      // chain A: verts 0..8   (edges 0..7)
    INITV(8, TB, CB, SB);      // chain B: verts 8..15, 17(wrap)

#pragma unroll
    for (int i = 0; i < EPC; ++i) {
        const int offA = i + 1;                        // 1..8
        const int offB = (i == EPC - 1) ? 17 : 9 + i;  // 9..15, then 17 (wrap)
        STEP(TA, CA, SA, offA, i,     aR0, aI0);
        STEP(TB, CB, SB, offB, 8 + i, aR1, aI1);
    }

    u64 accR = f2add(aR0, aR1);
    u64 accI = f2add(aI0, aI1);   // holds -Im

    // ---- reduce the 32 lanes (packed) ----
#pragma unroll
    for (int off = 16; off > 0; off >>= 1) {
        accR = f2add(accR, __shfl_down_sync(0xFFFFFFFFu, accR, off));
        accI = f2add(accI, __shfl_down_sync(0xFFFFFFFFu, accI, off));
    }

    if (lane == 0) {
        // F = -einsum * RES^J ; (2*pi)^-2 folded into SCALE. accI = -Im.
        const float SCALE = (float)(-16384.0 / (4.0 * 3.14159265358979323846
                                                    * 3.14159265358979323846));
        float aRlo, aRhi, aIlo, aIhi;
        upk(accR, aRlo, aRhi);
        upk(accI, aIlo, aIhi);
        float oRlo =  SCALE * aRlo, oRhi =  SCALE * aRhi;
        float oIlo = -SCALE * aIlo, oIhi = -SCALE * aIhi;

        if (fp == 0) {
            // DC: F[:,0,0,:,:] = 8192*sum(C*D) in BOTH re and im
            float s = 0.0f;
#pragma unroll 8
            for (int e = 0; e < NE; ++e) s += sCD[e + (e >> 4)];
            oRlo = 8192.0f * s;
            oIlo = oRlo;
        }

        int obase = ((b * FX + fx0) * FY2 + fy) * 2;
        out[obase + 0] = oRlo;
        out[obase + 1] = oIlo;
        out[obase + 2 * FY2 + 0] = oRhi;   // fx0 + 1
        out[obase + 2 * FY2 + 1] = oIhi;
    }
}

extern "C" void kernel_launch(void* const* d_in, const int* in_sizes, int n_in,
                              void* d_out, int out_size)
{
    const float* V = (const float*)d_in[0];
    const int*   E = (const int*)  d_in[1];
    const float* D = (const float*)d_in[2];
    float* out = (float*)d_out;

    const int B = in_sizes[0] / (NV * 2);   // 2
    dim3 grid(NFP / GROUPS, B);             // (520, 2) = 1040 blocks
    ddsl_spec_kernel<<<grid, BLOCK>>>(V, E, D, out);
}

// round 15
// speedup vs baseline: 1.0212x; 1.0212x over previous
#include <cuda_runtime.h>
#include <math.h>

// DDSL spec: B=2, NV=NE=512, RES=(128,128) -> freq grid 128 x 65, J=2.
// kx-QUAD kernel: each warp owns 4 adjacent fx freqs (kx..kx+3) x one ky.
// One vertex sincos serves all 4 freqs via precomputed per-vertex rotations
// (cos/sin 2pi*x and double-angle): t_{+j} = t + j*x. Packed f32x2 math in
// two pairs (kx,kx+1) and (kx+2,kx+3). 16 edges/lane in two independent
// 8-edge ring chains (stride-17 padded layout, compile-time offsets).

#define NV      512
#define NE      512
#define FX      128
#define FY2     65
#define NFQ     (FX / 4 * FY2)      // 2080 fx-quads
#define GROUPS  8                   // quads (warps) per block
#define BLOCK   256
#define EPC     8                   // edges per chain (2 chains per lane)

typedef unsigned long long u64;

__device__ __forceinline__ u64 pk2(float a, float b) {
    u64 r; asm("mov.b64 %0, {%1, %2};" : "=l"(r) : "f"(a), "f"(b)); return r;
}
__device__ __forceinline__ void upk(u64 v, float& a, float& b) {
    asm("mov.b64 {%0, %1}, %2;" : "=f"(a), "=f"(b) : "l"(v));
}
__device__ __forceinline__ u64 f2fma(u64 a, u64 b, u64 c) {
    u64 d; asm("fma.rn.f32x2 %0, %1, %2, %3;" : "=l"(d) : "l"(a), "l"(b), "l"(c)); return d;
}
__device__ __forceinline__ u64 f2add(u64 a, u64 b) {
    u64 d; asm("add.rn.f32x2 %0, %1, %2;" : "=l"(d) : "l"(a), "l"(b)); return d;
}
__device__ __forceinline__ u64 f2mul(u64 a, u64 b) {
    u64 d; asm("mul.rn.f32x2 %0, %1, %2;" : "=l"(d) : "l"(a), "l"(b)); return d;
}

__device__ __forceinline__ float fracr(float t) {
    const float MAGIC = 12582912.0f;  // 1.5 * 2^23
    float g = __fadd_rn(t, MAGIC);
    float r = __fadd_rn(g, -MAGIC);
    return t - r;
}

__global__ __launch_bounds__(BLOCK, 4)
void ddsl_spec_kernel(const float* __restrict__ V,
                      const int*   __restrict__ E,
                      const float* __restrict__ D,
                      float*       __restrict__ out)
{
    // pad-every-16 layout: idx(e) = e + (e>>4); lane group stride = 17.
    __shared__ float4 sA[546];     // (x, y, cos2pix, sin2pix); idx 544 = wrap
    __shared__ float4 sB[546];     // (cos4pix, sin4pix, 2x, 0)
    __shared__ float  sCD[544];    // C*D per edge

    const int b = blockIdx.y;
    const float TWO_PI = 6.28318530717958647692f;

    // ---- stage ring vertices + per-vertex phases + C*D ----
    for (int e = threadIdx.x; e < NE; e += BLOCK) {
        int i0 = E[(b * NE + e) * 2 + 0];
        int i1 = E[(b * NE + e) * 2 + 1];
        float ax = V[(b * NV + i0) * 2 + 0];
        float ay = V[(b * NV + i0) * 2 + 1];
        float bx = V[(b * NV + i1) * 2 + 0];
        float by = V[(b * NV + i1) * 2 + 1];
        int p = e + (e >> 4);
        float sx, cx;
        __sincosf(fracr(ax) * TWO_PI, &sx, &cx);     // sin first, cos second
        float c2x = fmaf(cx, cx, -sx * sx);          // double angle
        float s2x = 2.0f * sx * cx;
        sA[p] = make_float4(ax, ay, cx, sx);
        sB[p] = make_float4(c2x, s2x, ax + ax, 0.0f);
        sCD[p] = (ax * by - ay * bx) * D[b * NE + e];
        if (e == 0) {
            sA[544] = make_float4(ax, ay, cx, sx);
            sB[544] = make_float4(c2x, s2x, ax + ax, 0.0f);
        }
    }
    __syncthreads();

    const int lane = threadIdx.x & 31;
    const int fp   = blockIdx.x * GROUPS + (threadIdx.x >> 5);  // quad index

    const int fxq = fp / FY2;            // 0..31
    const int fy  = fp - fxq * FY2;
    const int fx0 = 4 * fxq;
    const int kx0 = (fx0 < FX / 2) ? fx0 : fx0 - FX;   // quad = kx0..kx0+3
    const float fkx = (float)kx0;
    const float fky = (float)fy;

    const u64 NEG1 = pk2(-1.0f, -1.0f);

    const float4* ab = &sA[17 * lane];
    const float4* bb = &sB[17 * lane];
    const float*  cb = &sCD[17 * lane];

    u64 aR01 = pk2(0.0f, 0.0f), aI01 = pk2(0.0f, 0.0f);
    u64 aR23 = pk2(0.0f, 0.0f), aI23 = pk2(0.0f, 0.0f);

    // build vertex state (4 phases) at shared offset OFS
#define MKVERT(OFS, T01, T23, C01, C23, S01, S23)                          \
    {                                                                      \
        float4 a = ab[OFS];                                                \
        float4 q = bb[OFS];                                                \
        float tl = fmaf(a.y, fky, a.x * fkx);                              \
        float sl, cl;                                                      \
        __sincosf(fracr(tl) * TWO_PI, &sl, &cl);                           \
        float c1 = fmaf(cl, a.z, -sl * a.w);                               \
        float s1 = fmaf(sl, a.z,  cl * a.w);                               \
        float c2 = fmaf(cl, q.x, -sl * q.y);                               \
        float s2 = fmaf(sl, q.x,  cl * q.y);                               \
        float c3 = fmaf(c2, a.z, -s2 * a.w);                               \
        float s3 = fmaf(s2, a.z,  c2 * a.w);                               \
        float t1 = tl + a.x;                                               \
        float t2 = tl + q.z;                                               \
        float t3 = t2 + a.x;                                               \
        T01 = pk2(tl, t1); T23 = pk2(t2, t3);                              \
        C01 = pk2(cl, c1); C23 = pk2(c2, c3);                              \
        S01 = pk2(sl, s1); S23 = pk2(s2, s3);                              \
    }

    // one packed-pair edge eval; SANIT guards the systematic k=(0,0) zero
#define PAIR(T, C, S, NT, NC, NS, CD, AR, AI, SANIT)                       \
    {                                                                      \
        u64 dt  = f2fma(NT, NEG1, T);                                      \
        u64 den = f2mul(f2mul(T, NT), dt);                                 \
        u64 nt_ = f2mul(T, NEG1);                                          \
        u64 nr  = f2fma(NC, nt_, f2fma(C, NT, dt));                        \
        u64 ni  = f2fma(NS, nt_, f2mul(S, NT));                            \
        float dlo, dhi; upk(den, dlo, dhi);                                \
        if (SANIT) dlo = (dlo == 0.0f) ? 1.0f : dlo;                       \
        float rp = __fdividef(CD, dlo * dhi);                              \
        u64 rc = pk2(rp * dhi, rp * dlo);                                  \
        AR = f2fma(nr, rc, AR);                                            \
        AI = f2fma(ni, rc, AI);                                            \
    }

    // advance one chain by one edge (4 freq evals)
#define STEP(T01, T23, C01, C23, S01, S23, OFS, CDOFS)                     \
    {                                                                      \
        u64 nT01, nT23, nC01, nC23, nS01, nS23;                            \
        MKVERT(OFS, nT01, nT23, nC01, nC23, nS01, nS23);                   \
        float cd = cb[CDOFS];                                              \
        PAIR(T01, C01, S01, nT01, nC01, nS01, cd, aR01, aI01, 1);          \
        PAIR(T23, C23, S23, nT23, nC23, nS23, cd, aR23, aI23, 0);          \
        T01 = nT01; T23 = nT23;                                            \
        C01 = nC01; C23 = nC23;                                            \
        S01 = nS01; S23 = nS23;                                            \
    }

    u64 TA01, TA23, CA01, CA23, SA01, SA23;
    u64 TB01, TB23, CB01, CB23, SB01, SB23;
    MKVERT(0, TA01, TA23, CA01, CA23, SA01, SA23);   // chain A verts 0..8
    MKVERT(8, TB01, TB23, CB01, CB23, SB01, SB23);   // chain B verts 8..15,17

#pragma unroll
    for (int i = 0; i < EPC; ++i) {
        const int offA = i + 1;                        // 1..8
        const int offB = (i == EPC - 1) ? 17 : 9 + i;  // 9..15, then 17 (wrap)
        STEP(TA01, TA23, CA01, CA23, SA01, SA23, offA, i);
        STEP(TB01, TB23, CB01, CB23, SB01, SB23, offB, 8 + i);
    }

    // ---- reduce the 32 lanes (packed) ----
#pragma unroll
    for (int off = 16; off > 0; off >>= 1) {
        aR01 = f2add(aR01, __shfl_down_sync(0xFFFFFFFFu, aR01, off));
        aI01 = f2add(aI01, __shfl_down_sync(0xFFFFFFFFu, aI01, off));
        aR23 = f2add(aR23, __shfl_down_sync(0xFFFFFFFFu, aR23, off));
        aI23 = f2add(aI23, __shfl_down_sync(0xFFFFFFFFu, aI23, off));
    }

    if (lane == 0) {
        // F = -einsum * RES^J ; (2*pi)^-2 folded into SCALE. aI holds -Im.
        const float SCALE = (float)(-16384.0 / (4.0 * 3.14159265358979323846
                                                    * 3.14159265358979323846));
        float r0, r1, r2, r3, i0v, i1v, i2v, i3v;
        upk(aR01, r0, r1); upk(aR23, r2, r3);
        upk(aI01, i0v, i1v); upk(aI23, i2v, i3v);
        float oR[4] = { SCALE * r0,  SCALE * r1,  SCALE * r2,  SCALE * r3 };
        float oI[4] = {-SCALE * i0v, -SCALE * i1v, -SCALE * i2v, -SCALE * i3v};

        if (fp == 0) {
            // DC: F[:,0,0,:,:] = 8192*sum(C*D) in BOTH re and im
            float s = 0.0f;
#pragma unroll 8
            for (int e = 0; e < NE; ++e) s += sCD[e + (e >> 4)];
            oR[0] = 8192.0f * s;
            oI[0] = oR[0];
        }

        int obase = ((b * FX + fx0) * FY2 + fy) * 2;
#pragma unroll
        for (int j = 0; j < 4; ++j) {
            out[obase + j * 2 * FY2 + 0] = oR[j];
            out[obase + j * 2 * FY2 + 1] = oI[j];
        }
    }
}

extern "C" void kernel_launch(void* const* d_in, const int* in_sizes, int n_in,
                              void* d_out, int out_size)
{
    const float* V = (const float*)d_in[0];
    const int*   E = (const int*)  d_in[1];
    const float* D = (const float*)d_in[2];
    float* out = (float*)d_out;

    const int B = in_sizes[0] / (NV * 2);   // 2
    dim3 grid(NFQ / GROUPS, B);             // (260, 2) = 520 blocks
    ddsl_spec_kernel<<<grid, BLOCK>>>(V, E, D, out);
}